// round 13
// baseline (speedup 1.0000x reference)
#include <cuda_runtime.h>
#include <cuda_bf16.h>
#include <cuda_fp16.h>
#include <cstdint>

#define BHN 32
#define SEQ 2048
#define DIM 128
#define NTOK (BHN*SEQ)          // 65536
#define NELEM (NTOK*DIM)        // 8388608

// ---- scratch (static device globals; no runtime allocation) ----
__device__ float g_kd[NELEM];
__device__ float g_vd[NELEM];
__device__ unsigned int g_absmax[2];
__device__ __align__(16) __half g_qf[NELEM];
__device__ __align__(16) __half g_kf[NELEM];
__device__ __align__(16) __half g_vf[NELEM];
__device__ __align__(16) __half g_of[NELEM];
// pre-swizzled fp16 hi/lo rotation operands (B layout [n][k], 256B pitch)
__device__ __align__(16) __half g_Rf_hi[DIM*DIM];
__device__ __align__(16) __half g_Rf_lo[DIM*DIM];
__device__ __align__(16) __half g_Ri_hi[DIM*DIM];
__device__ __align__(16) __half g_Ri_lo[DIM*DIM];

// 1/sqrt(128) * log2(e): fold into Q so softmax is a bare ex2
#define QSCL 0.12751744750522672f

// ================= helpers =================
__device__ __forceinline__ uint32_t smem_u32(const void* p) {
    uint32_t a;
    asm("{ .reg .u64 t; cvta.to.shared.u64 t, %1; cvt.u32.u64 %0, t; }" : "=r"(a) : "l"(p));
    return a;
}
__device__ __forceinline__ void ldm_x4(uint32_t* r, uint32_t addr) {
    asm volatile("ldmatrix.sync.aligned.m8n8.x4.shared.b16 {%0,%1,%2,%3}, [%4];"
        : "=r"(r[0]), "=r"(r[1]), "=r"(r[2]), "=r"(r[3]) : "r"(addr));
}
__device__ __forceinline__ void ldm_x4t(uint32_t* r, uint32_t addr) {
    asm volatile("ldmatrix.sync.aligned.m8n8.x4.trans.shared.b16 {%0,%1,%2,%3}, [%4];"
        : "=r"(r[0]), "=r"(r[1]), "=r"(r[2]), "=r"(r[3]) : "r"(addr));
}
__device__ __forceinline__ void mma16816h(float* c, const uint32_t* a, const uint32_t* b) {
    asm volatile("mma.sync.aligned.m16n8k16.row.col.f32.f16.f16.f32 "
        "{%0,%1,%2,%3}, {%4,%5,%6,%7}, {%8,%9}, {%0,%1,%2,%3};"
        : "+f"(c[0]), "+f"(c[1]), "+f"(c[2]), "+f"(c[3])
        : "r"(a[0]), "r"(a[1]), "r"(a[2]), "r"(a[3]), "r"(b[0]), "r"(b[1]));
}
__device__ __forceinline__ float ex2(float x) {
    float y;
    asm("ex2.approx.f32 %0, %1;" : "=f"(y) : "f"(x));
    return y;
}
__device__ __forceinline__ uint32_t hpack(float a, float b) {
    __half2 h = __floats2half2_rn(a, b);
    return *reinterpret_cast<uint32_t*>(&h);
}
__device__ __forceinline__ void split2(float2 p, uint32_t& hi, uint32_t& lo) {
    __half2 h = __floats2half2_rn(p.x, p.y);
    hi = *reinterpret_cast<uint32_t*>(&h);
    lo = hpack(p.x - __half2float(h.x), p.y - __half2float(h.y));
}
__device__ __forceinline__ void cpa16(uint32_t d, const void* s) {
    asm volatile("cp.async.cg.shared.global [%0], [%1], 16;" :: "r"(d), "l"(s));
}
__device__ __forceinline__ void cpa_commit() {
    asm volatile("cp.async.commit_group;" ::: "memory");
}
template<int N> __device__ __forceinline__ void cpa_wait() {
    asm volatile("cp.async.wait_group %0;" :: "n"(N) : "memory");
}

// ------------------------------------------------------------------
// Build pre-swizzled fp16 hi/lo B operands; also reset absmax.
__global__ void prepR_kernel(const float* __restrict__ R) {
    int idx = blockIdx.x * 128 + threadIdx.x;   // 16384
    if (idx < 2) g_absmax[idx] = 0u;
    int n = idx >> 7, k = idx & 127;
    float fv = R[k*DIM + n];   // Bfwd[n][k] = R[k][n]
    float iv = R[n*DIM + k];   // Binv[n][k] = R[n][k]
    int c = k >> 3;
    uint32_t off = (uint32_t)(n*256 + ((c ^ (n & 7)) << 4) + (k & 7)*2);
    __half fh = __float2half_rn(fv);
    __half ih = __float2half_rn(iv);
    *reinterpret_cast<__half*>(reinterpret_cast<char*>(g_Rf_hi) + off) = fh;
    *reinterpret_cast<__half*>(reinterpret_cast<char*>(g_Rf_lo) + off) = __float2half_rn(fv - __half2float(fh));
    *reinterpret_cast<__half*>(reinterpret_cast<char*>(g_Ri_hi) + off) = ih;
    *reinterpret_cast<__half*>(reinterpret_cast<char*>(g_Ri_lo) + off) = __float2half_rn(iv - __half2float(ih));
}

// ===================== HMMA forward rotation (fused q/k/v) =====================
// 128 rows/CTA, 512 threads (16 warps). warp w: rows (w&7)*16, n-half (w>>3)*64.
// R loaded once per 128 rows (half the L2 traffic of the 64-row version).
// blockIdx.y: 0=q (fp16 out, pre-scaled by QSCL), 1=k, 2=v (fp32 out + absmax).
#define ROT_SMEM 65536   // R hi 32KB + R lo 32KB
__global__ void __launch_bounds__(512, 1) rotfwd_kernel(
    const float* __restrict__ xq, const float* __restrict__ xk, const float* __restrict__ xv)
{
    extern __shared__ char smc[];
    uint32_t smb = smem_u32(smc);
    int which = blockIdx.y;
    const float* x = (which == 0) ? xq : (which == 1) ? xk : xv;
    int tid = threadIdx.x;
    int w = tid >> 5, lane = tid & 31;
    int gq = lane >> 2, tg = lane & 3;
    int l8 = lane & 7, g8 = lane >> 3;
    int gb = g8 >> 1, gA = g8 & 1;
    int h  = w >> 3;
    int wr = (w & 7) * 16;
    int m0 = blockIdx.x * 128;

    for (int f = tid; f < 2048; f += 512) {
        cpa16(smb + f*16,         reinterpret_cast<const char*>(g_Rf_hi) + f*16);
        cpa16(smb + 32768 + f*16, reinterpret_cast<const char*>(g_Rf_lo) + f*16);
    }
    cpa_commit();

    uint32_t ah[8][4], al[8][4];
    {
        const float* xr0 = x + (size_t)(m0 + wr + gq) * DIM;
        const float* xr8 = xr0 + 8 * DIM;
        #pragma unroll
        for (int k8 = 0; k8 < 8; k8++) {
            int c0 = k8*16 + tg*2;
            float2 p00 = *reinterpret_cast<const float2*>(xr0 + c0);
            float2 p10 = *reinterpret_cast<const float2*>(xr8 + c0);
            float2 p01 = *reinterpret_cast<const float2*>(xr0 + c0 + 8);
            float2 p11 = *reinterpret_cast<const float2*>(xr8 + c0 + 8);
            split2(p00, ah[k8][0], al[k8][0]);
            split2(p10, ah[k8][1], al[k8][1]);
            split2(p01, ah[k8][2], al[k8][2]);
            split2(p11, ah[k8][3], al[k8][3]);
        }
    }

    cpa_wait<0>();
    __syncthreads();

    float acc[32];
    #pragma unroll
    for (int i = 0; i < 32; i++) acc[i] = 0.0f;

    #pragma unroll
    for (int k8 = 0; k8 < 8; k8++) {
        #pragma unroll
        for (int np = 0; np < 4; np++) {
            int brow = h*64 + np*16 + (gb << 3) + l8;
            int ch = k8*2 + gA;
            uint32_t off = brow*256 + ((ch ^ (brow & 7)) << 4);
            uint32_t bh[4], bl[4];
            ldm_x4(bh, smb + off);
            ldm_x4(bl, smb + 32768 + off);
            mma16816h(&acc[np*8],     ah[k8], bh);
            mma16816h(&acc[np*8 + 4], ah[k8], bh + 2);
            mma16816h(&acc[np*8],     ah[k8], bl);
            mma16816h(&acc[np*8 + 4], ah[k8], bl + 2);
            mma16816h(&acc[np*8],     al[k8], bh);
            mma16816h(&acc[np*8 + 4], al[k8], bh + 2);
        }
    }

    if (which > 0) {
        float mx = 0.0f;
        #pragma unroll
        for (int i = 0; i < 32; i++) mx = fmaxf(mx, fabsf(acc[i]));
        #pragma unroll
        for (int o = 16; o; o >>= 1) mx = fmaxf(mx, __shfl_xor_sync(0xffffffffu, mx, o));
        __shared__ float red[16];
        if (lane == 0) red[w] = mx;
        __syncthreads();
        if (tid == 0) {
            float m = red[0];
            #pragma unroll
            for (int i = 1; i < 16; i++) m = fmaxf(m, red[i]);
            atomicMax(&g_absmax[which - 1], __float_as_uint(m));
        }
    }

    int rA = m0 + wr + gq;
    int col0 = h*64 + tg*2;
    if (which == 0) {
        __half* hA = g_qf + (size_t)rA * DIM + col0;
        __half* hB = hA + 8 * DIM;
        #pragma unroll
        for (int nb = 0; nb < 8; nb++) {
            *reinterpret_cast<uint32_t*>(hA + nb*8) = hpack(acc[nb*4+0]*QSCL, acc[nb*4+1]*QSCL);
            *reinterpret_cast<uint32_t*>(hB + nb*8) = hpack(acc[nb*4+2]*QSCL, acc[nb*4+3]*QSCL);
        }
    } else {
        float* fA = ((which == 1) ? g_kd : g_vd) + (size_t)rA * DIM + col0;
        float* fB = fA + 8 * DIM;
        #pragma unroll
        for (int nb = 0; nb < 8; nb++) {
            *reinterpret_cast<float2*>(fA + nb*8) = make_float2(acc[nb*4+0], acc[nb*4+1]);
            *reinterpret_cast<float2*>(fB + nb*8) = make_float2(acc[nb*4+2], acc[nb*4+3]);
        }
    }
}

// ===================== HMMA inverse rotation (fp16 in, fp32 out) =====================
// 128 rows/CTA, 512 threads (16 warps).
__global__ void __launch_bounds__(512, 1) rotinv_kernel(
    const __half* __restrict__ xh, float* __restrict__ yf)
{
    extern __shared__ char smc[];
    uint32_t smb = smem_u32(smc);
    int tid = threadIdx.x;
    int w = tid >> 5, lane = tid & 31;
    int gq = lane >> 2, tg = lane & 3;
    int l8 = lane & 7, g8 = lane >> 3;
    int gb = g8 >> 1, gA = g8 & 1;
    int h  = w >> 3;
    int wr = (w & 7) * 16;
    int m0 = blockIdx.x * 128;

    for (int f = tid; f < 2048; f += 512) {
        cpa16(smb + f*16,         reinterpret_cast<const char*>(g_Ri_hi) + f*16);
        cpa16(smb + 32768 + f*16, reinterpret_cast<const char*>(g_Ri_lo) + f*16);
    }
    cpa_commit();

    uint32_t ah[8][4];
    {
        const __half* xr0 = xh + (size_t)(m0 + wr + gq) * DIM;
        const __half* xr8 = xr0 + 8 * DIM;
        #pragma unroll
        for (int k8 = 0; k8 < 8; k8++) {
            int c0 = k8*16 + tg*2;
            ah[k8][0] = *reinterpret_cast<const uint32_t*>(xr0 + c0);
            ah[k8][1] = *reinterpret_cast<const uint32_t*>(xr8 + c0);
            ah[k8][2] = *reinterpret_cast<const uint32_t*>(xr0 + c0 + 8);
            ah[k8][3] = *reinterpret_cast<const uint32_t*>(xr8 + c0 + 8);
        }
    }

    cpa_wait<0>();
    __syncthreads();

    float acc[32];
    #pragma unroll
    for (int i = 0; i < 32; i++) acc[i] = 0.0f;

    #pragma unroll
    for (int k8 = 0; k8 < 8; k8++) {
        #pragma unroll
        for (int np = 0; np < 4; np++) {
            int brow = h*64 + np*16 + (gb << 3) + l8;
            int ch = k8*2 + gA;
            uint32_t off = brow*256 + ((ch ^ (brow & 7)) << 4);
            uint32_t bh[4], bl[4];
            ldm_x4(bh, smb + off);
            ldm_x4(bl, smb + 32768 + off);
            mma16816h(&acc[np*8],     ah[k8], bh);
            mma16816h(&acc[np*8 + 4], ah[k8], bh + 2);
            mma16816h(&acc[np*8],     ah[k8], bl);
            mma16816h(&acc[np*8 + 4], ah[k8], bl + 2);
        }
    }

    int rA = m0 + wr + gq;
    int col0 = h*64 + tg*2;
    float* fA = yf + (size_t)rA * DIM + col0;
    float* fB = fA + 8 * DIM;
    #pragma unroll
    for (int nb = 0; nb < 8; nb++) {
        *reinterpret_cast<float2*>(fA + nb*8) = make_float2(acc[nb*4+0], acc[nb*4+1]);
        *reinterpret_cast<float2*>(fB + nb*8) = make_float2(acc[nb*4+2], acc[nb*4+3]);
    }
}

// quant + dequant -> single fp16 (fused K/V via blockIdx.y, MLP=4)
__global__ void __launch_bounds__(256) quant_kernel(const float* __restrict__ qjl)
{
    int which = blockIdx.y;
    const float* xdat = which ? g_vd : g_kd;
    __half* out = which ? g_vf : g_kf;
    float xmax = __uint_as_float(g_absmax[which]) + 1e-8f;
    float qsc  = qjl[0] * xmax;
    size_t base = (size_t)blockIdx.x * 1024 + threadIdx.x;

    float4 v[4];
    #pragma unroll
    for (int u = 0; u < 4; u++)
        v[u] = reinterpret_cast<const float4*>(xdat)[base + u*256];

    #pragma unroll
    for (int u = 0; u < 4; u++) {
        float vv[4] = {v[u].x, v[u].y, v[u].z, v[u].w};
        #pragma unroll
        for (int t = 0; t < 4; t++) {
            float xs = vv[t] / xmax * 3.5f;
            float xq = rintf(xs * 4.0f) * 0.25f;
            xq = fminf(3.5f, fmaxf(-3.5f, xq));
            float r  = xs - xq;
            float sg = (r > 0.0f) ? 1.0f : ((r < 0.0f) ? -1.0f : 0.0f);
            vv[t] = (xq + sg * qsc) / 3.5f * xmax;
        }
        reinterpret_cast<uint2*>(out)[base + u*256] =
            make_uint2(hpack(vv[0], vv[1]), hpack(vv[2], vv[3]));
    }
}

// ===================== HMMA flash attention (fp16, 3-stage, 2 CTA/SM) =====================
// BM=64 (4 warps x 16 rows), BN=64 keys/tile, 32 tiles. 128 threads, 2 CTAs/SM.
// Q pre-scaled by QSCL -> softmax is bare ex2.
#define STG   32768
#define SVH   16384
#define ATT_SMEM (3*STG)
__global__ void __launch_bounds__(128, 2) attn_kernel(
    const __half* __restrict__ qf_g, const __half* __restrict__ kf_g,
    const __half* __restrict__ vf_g, __half* __restrict__ og)
{
    extern __shared__ char smc[];
    uint32_t smb = smem_u32(smc);

    int tid = threadIdx.x;
    int w = tid >> 5, lane = tid & 31;
    int l = lane & 7, g = lane >> 3;
    int ga = (g & 1) << 3;
    int gb = g >> 1;

    size_t base = (size_t)blockIdx.y * SEQ * DIM;
    int q0 = blockIdx.x * 64;

    // ---- load Q fragments via smem staging (stage-0 region) ----
    uint32_t qf[8][4];
    {
        for (int f = tid; f < 1024; f += 128) {
            int r = f >> 4, c = f & 15;
            *reinterpret_cast<uint4*>(smc + r*256 + ((c ^ (r & 7)) << 4)) =
                *reinterpret_cast<const uint4*>(qf_g + base + (size_t)(q0 + r)*DIM + c*8);
        }
        __syncthreads();
        int row = w*16 + ga + l;
        uint32_t rbase = smb + row*256;
        int rx = row & 7;
        #pragma unroll
        for (int k8 = 0; k8 < 8; k8++) {
            int ch = k8*2 + gb;
            ldm_x4(qf[k8], rbase + ((ch ^ rx) << 4));
        }
        __syncthreads();
    }

    // ---- prefetch tiles 0,1 into stages 0,1 ----
    #pragma unroll
    for (int pt = 0; pt < 2; pt++) {
        uint32_t sb = smb + pt * STG;
        int kt = pt * 64;
        #pragma unroll
        for (int it = 0; it < 8; it++) {
            int f = tid + it*128;
            int r = f >> 4, c = f & 15;
            size_t gi = base + (size_t)(kt + r)*DIM + c*8;
            uint32_t so = r*256 + ((c ^ (r & 7)) << 4);
            cpa16(sb + so,       kf_g + gi);
            cpa16(sb + SVH + so, vf_g + gi);
        }
        cpa_commit();
    }

    float o[64];
    #pragma unroll
    for (int i = 0; i < 64; i++) o[i] = 0.0f;
    float lsA = 0.0f, lsB = 0.0f;

    int cur = 0, nxt2 = 2;
    for (int t = 0; t < 32; t++) {
        if (t < 30) {
            uint32_t sb = smb + nxt2 * STG;
            int kt2 = (t + 2) * 64;
            #pragma unroll
            for (int it = 0; it < 8; it++) {
                int f = tid + it*128;
                int r = f >> 4, c = f & 15;
                size_t gi = base + (size_t)(kt2 + r)*DIM + c*8;
                uint32_t so = r*256 + ((c ^ (r & 7)) << 4);
                cpa16(sb + so,       kf_g + gi);
                cpa16(sb + SVH + so, vf_g + gi);
            }
            cpa_commit();
            cpa_wait<2>();
        } else if (t == 30) {
            cpa_wait<1>();
        } else {
            cpa_wait<0>();
        }
        __syncthreads();

        uint32_t kb = smb + cur * STG;

        // ---- S = Qf * Kf ----
        float s[32];
        #pragma unroll
        for (int i = 0; i < 32; i++) s[i] = 0.0f;
        #pragma unroll
        for (int k8 = 0; k8 < 8; k8++) {
            #pragma unroll
            for (int np = 0; np < 4; np++) {
                int row = np*16 + (gb << 3) + l;
                int ch = k8*2 + (g & 1);
                uint32_t b[4];
                ldm_x4(b, kb + row*256 + ((ch ^ (row & 7)) << 4));
                mma16816h(&s[np*8],     qf[k8], b);
                mma16816h(&s[np*8 + 4], qf[k8], b + 2);
            }
        }

        // ---- softmax: p = 2^s (Q pre-scaled) ----
        #pragma unroll
        for (int nb = 0; nb < 8; nb++) {
            float p0 = ex2(s[nb*4+0]), p1 = ex2(s[nb*4+1]);
            float p2 = ex2(s[nb*4+2]), p3 = ex2(s[nb*4+3]);
            s[nb*4+0] = p0; s[nb*4+1] = p1; s[nb*4+2] = p2; s[nb*4+3] = p3;
            lsA += p0 + p1;
            lsB += p2 + p3;
        }
        uint32_t pf[4][4];
        #pragma unroll
        for (int kk = 0; kk < 4; kk++) {
            pf[kk][0] = hpack(s[8*kk+0], s[8*kk+1]);
            pf[kk][1] = hpack(s[8*kk+2], s[8*kk+3]);
            pf[kk][2] = hpack(s[8*kk+4], s[8*kk+5]);
            pf[kk][3] = hpack(s[8*kk+6], s[8*kk+7]);
        }

        // ---- O += Pf * Vf ----
        {
            uint32_t vb = kb + SVH;
            #pragma unroll
            for (int kk = 0; kk < 4; kk++) {
                #pragma unroll
                for (int nd = 0; nd < 8; nd++) {
                    int row = kk*16 + ga + l;
                    int ch = nd*2 + gb;
                    uint32_t b[4];
                    ldm_x4t(b, vb + row*256 + ((ch ^ (row & 7)) << 4));
                    mma16816h(&o[nd*8],     pf[kk], b);
                    mma16816h(&o[nd*8 + 4], pf[kk], b + 2);
                }
            }
        }
        __syncthreads();

        if (++cur == 3) cur = 0;
        if (++nxt2 == 3) nxt2 = 0;
    }

    // ---- epilogue: normalize, store fp16 ----
    lsA += __shfl_xor_sync(0xffffffffu, lsA, 1);
    lsA += __shfl_xor_sync(0xffffffffu, lsA, 2);
    lsB += __shfl_xor_sync(0xffffffffu, lsB, 1);
    lsB += __shfl_xor_sync(0xffffffffu, lsB, 2);
    float invA = 1.0f / lsA, invB = 1.0f / lsB;

    int rA = q0 + w*16 + (lane >> 2);
    int col0 = (lane & 3) * 2;
    __half* opA = og + base + (size_t)rA * DIM + col0;
    __half* opB = opA + 8 * DIM;
    #pragma unroll
    for (int nb = 0; nb < 16; nb++) {
        *reinterpret_cast<uint32_t*>(opA + nb*8) = hpack(o[nb*4+0]*invA, o[nb*4+1]*invA);
        *reinterpret_cast<uint32_t*>(opB + nb*8) = hpack(o[nb*4+2]*invB, o[nb*4+3]*invB);
    }
}

// ------------------------------------------------------------------
extern "C" void kernel_launch(void* const* d_in, const int* in_sizes, int n_in,
                              void* d_out, int out_size)
{
    const float* q   = (const float*)d_in[0];
    const float* k   = (const float*)d_in[1];
    const float* v   = (const float*)d_in[2];
    const float* R   = (const float*)d_in[3];
    const float* qjl = (const float*)d_in[4];

    __half *qf, *kf, *vf, *of;
    cudaGetSymbolAddress((void**)&qf, g_qf);
    cudaGetSymbolAddress((void**)&kf, g_kf);
    cudaGetSymbolAddress((void**)&vf, g_vf);
    cudaGetSymbolAddress((void**)&of, g_of);

    cudaFuncSetAttribute(rotfwd_kernel, cudaFuncAttributeMaxDynamicSharedMemorySize, ROT_SMEM);
    cudaFuncSetAttribute(rotinv_kernel, cudaFuncAttributeMaxDynamicSharedMemorySize, ROT_SMEM);
    cudaFuncSetAttribute(attn_kernel,   cudaFuncAttributeMaxDynamicSharedMemorySize, ATT_SMEM);

    prepR_kernel<<<128, 128>>>(R);

    rotfwd_kernel<<<dim3(NTOK/128, 3), 512, ROT_SMEM>>>(q, k, v);

    quant_kernel<<<dim3(NELEM/4/1024, 2), 256>>>(qjl);

    attn_kernel<<<dim3(SEQ/64, BHN), 128, ATT_SMEM>>>(qf, kf, vf, of);

    rotinv_kernel<<<NTOK/128, 512, ROT_SMEM>>>(of, (float*)d_out);
}

// round 14
// speedup vs baseline: 1.0835x; 1.0835x over previous
#include <cuda_runtime.h>
#include <cuda_bf16.h>
#include <cuda_fp16.h>
#include <cstdint>

#define BHN 32
#define SEQ 2048
#define DIM 128
#define NTOK (BHN*SEQ)          // 65536
#define NELEM (NTOK*DIM)        // 8388608

// ---- scratch (static device globals; no runtime allocation) ----
__device__ float g_kd[NELEM];
__device__ float g_vd[NELEM];
__device__ unsigned int g_absmax[2];
__device__ __align__(16) __half g_qf[NELEM];
__device__ __align__(16) __half g_kf[NELEM];
__device__ __align__(16) __half g_vf[NELEM];
// pre-swizzled fp16 hi/lo rotation operands (B layout [n][k], 256B pitch)
__device__ __align__(16) __half g_Rf_hi[DIM*DIM];
__device__ __align__(16) __half g_Rf_lo[DIM*DIM];
__device__ __align__(16) __half g_Ri_hi[DIM*DIM];
__device__ __align__(16) __half g_Ri_lo[DIM*DIM];

// 1/sqrt(128) * log2(e): fold into Q so softmax is a bare ex2
#define QSCL 0.12751744750522672f

// ================= helpers =================
__device__ __forceinline__ uint32_t smem_u32(const void* p) {
    uint32_t a;
    asm("{ .reg .u64 t; cvta.to.shared.u64 t, %1; cvt.u32.u64 %0, t; }" : "=r"(a) : "l"(p));
    return a;
}
__device__ __forceinline__ void ldm_x4(uint32_t* r, uint32_t addr) {
    asm volatile("ldmatrix.sync.aligned.m8n8.x4.shared.b16 {%0,%1,%2,%3}, [%4];"
        : "=r"(r[0]), "=r"(r[1]), "=r"(r[2]), "=r"(r[3]) : "r"(addr));
}
__device__ __forceinline__ void ldm_x4t(uint32_t* r, uint32_t addr) {
    asm volatile("ldmatrix.sync.aligned.m8n8.x4.trans.shared.b16 {%0,%1,%2,%3}, [%4];"
        : "=r"(r[0]), "=r"(r[1]), "=r"(r[2]), "=r"(r[3]) : "r"(addr));
}
__device__ __forceinline__ void mma16816h(float* c, const uint32_t* a, const uint32_t* b) {
    asm volatile("mma.sync.aligned.m16n8k16.row.col.f32.f16.f16.f32 "
        "{%0,%1,%2,%3}, {%4,%5,%6,%7}, {%8,%9}, {%0,%1,%2,%3};"
        : "+f"(c[0]), "+f"(c[1]), "+f"(c[2]), "+f"(c[3])
        : "r"(a[0]), "r"(a[1]), "r"(a[2]), "r"(a[3]), "r"(b[0]), "r"(b[1]));
}
__device__ __forceinline__ float ex2(float x) {
    float y;
    asm("ex2.approx.f32 %0, %1;" : "=f"(y) : "f"(x));
    return y;
}
__device__ __forceinline__ uint32_t hpack(float a, float b) {
    __half2 h = __floats2half2_rn(a, b);
    return *reinterpret_cast<uint32_t*>(&h);
}
__device__ __forceinline__ void split2(float2 p, uint32_t& hi, uint32_t& lo) {
    __half2 h = __floats2half2_rn(p.x, p.y);
    hi = *reinterpret_cast<uint32_t*>(&h);
    lo = hpack(p.x - __half2float(h.x), p.y - __half2float(h.y));
}
__device__ __forceinline__ void cpa16(uint32_t d, const void* s) {
    asm volatile("cp.async.cg.shared.global [%0], [%1], 16;" :: "r"(d), "l"(s));
}
__device__ __forceinline__ void cpa_commit() {
    asm volatile("cp.async.commit_group;" ::: "memory");
}
template<int N> __device__ __forceinline__ void cpa_wait() {
    asm volatile("cp.async.wait_group %0;" :: "n"(N) : "memory");
}

// ------------------------------------------------------------------
// Build pre-swizzled fp16 hi/lo B operands; also reset absmax.
__global__ void prepR_kernel(const float* __restrict__ R) {
    int idx = blockIdx.x * 128 + threadIdx.x;   // 16384
    if (idx < 2) g_absmax[idx] = 0u;
    int n = idx >> 7, k = idx & 127;
    float fv = R[k*DIM + n];   // Bfwd[n][k] = R[k][n]
    float iv = R[n*DIM + k];   // Binv[n][k] = R[n][k]
    int c = k >> 3;
    uint32_t off = (uint32_t)(n*256 + ((c ^ (n & 7)) << 4) + (k & 7)*2);
    __half fh = __float2half_rn(fv);
    __half ih = __float2half_rn(iv);
    *reinterpret_cast<__half*>(reinterpret_cast<char*>(g_Rf_hi) + off) = fh;
    *reinterpret_cast<__half*>(reinterpret_cast<char*>(g_Rf_lo) + off) = __float2half_rn(fv - __half2float(fh));
    *reinterpret_cast<__half*>(reinterpret_cast<char*>(g_Ri_hi) + off) = ih;
    *reinterpret_cast<__half*>(reinterpret_cast<char*>(g_Ri_lo) + off) = __float2half_rn(iv - __half2float(ih));
}

// ===================== HMMA forward rotation (fused q/k/v) =====================
// 64 rows/CTA, 256 threads (8 warps). warp w: rows (w&3)*16, n-half (w>>2)*64.
// blockIdx.y: 0=q (fp16 out, pre-scaled by QSCL), 1=k, 2=v (fp32 out + absmax).
#define ROT_SMEM 65536   // R hi 32KB + R lo 32KB
__global__ void __launch_bounds__(256, 2) rotfwd_kernel(
    const float* __restrict__ xq, const float* __restrict__ xk, const float* __restrict__ xv)
{
    extern __shared__ char smc[];
    uint32_t smb = smem_u32(smc);
    int which = blockIdx.y;
    const float* x = (which == 0) ? xq : (which == 1) ? xk : xv;
    int tid = threadIdx.x;
    int w = tid >> 5, lane = tid & 31;
    int gq = lane >> 2, tg = lane & 3;
    int l8 = lane & 7, g8 = lane >> 3;
    int gb = g8 >> 1, gA = g8 & 1;
    int h  = w >> 2;
    int wr = (w & 3) * 16;
    int m0 = blockIdx.x * 64;

    for (int f = tid; f < 2048; f += 256) {
        cpa16(smb + f*16,         reinterpret_cast<const char*>(g_Rf_hi) + f*16);
        cpa16(smb + 32768 + f*16, reinterpret_cast<const char*>(g_Rf_lo) + f*16);
    }
    cpa_commit();

    uint32_t ah[8][4], al[8][4];
    {
        const float* xr0 = x + (size_t)(m0 + wr + gq) * DIM;
        const float* xr8 = xr0 + 8 * DIM;
        #pragma unroll
        for (int k8 = 0; k8 < 8; k8++) {
            int c0 = k8*16 + tg*2;
            float2 p00 = *reinterpret_cast<const float2*>(xr0 + c0);
            float2 p10 = *reinterpret_cast<const float2*>(xr8 + c0);
            float2 p01 = *reinterpret_cast<const float2*>(xr0 + c0 + 8);
            float2 p11 = *reinterpret_cast<const float2*>(xr8 + c0 + 8);
            split2(p00, ah[k8][0], al[k8][0]);
            split2(p10, ah[k8][1], al[k8][1]);
            split2(p01, ah[k8][2], al[k8][2]);
            split2(p11, ah[k8][3], al[k8][3]);
        }
    }

    cpa_wait<0>();
    __syncthreads();

    float acc[32];
    #pragma unroll
    for (int i = 0; i < 32; i++) acc[i] = 0.0f;

    #pragma unroll
    for (int k8 = 0; k8 < 8; k8++) {
        #pragma unroll
        for (int np = 0; np < 4; np++) {
            int brow = h*64 + np*16 + (gb << 3) + l8;
            int ch = k8*2 + gA;
            uint32_t off = brow*256 + ((ch ^ (brow & 7)) << 4);
            uint32_t bh[4], bl[4];
            ldm_x4(bh, smb + off);
            ldm_x4(bl, smb + 32768 + off);
            mma16816h(&acc[np*8],     ah[k8], bh);
            mma16816h(&acc[np*8 + 4], ah[k8], bh + 2);
            mma16816h(&acc[np*8],     ah[k8], bl);
            mma16816h(&acc[np*8 + 4], ah[k8], bl + 2);
            mma16816h(&acc[np*8],     al[k8], bh);
            mma16816h(&acc[np*8 + 4], al[k8], bh + 2);
        }
    }

    if (which > 0) {
        float mx = 0.0f;
        #pragma unroll
        for (int i = 0; i < 32; i++) mx = fmaxf(mx, fabsf(acc[i]));
        #pragma unroll
        for (int o = 16; o; o >>= 1) mx = fmaxf(mx, __shfl_xor_sync(0xffffffffu, mx, o));
        __shared__ float red[8];
        if (lane == 0) red[w] = mx;
        __syncthreads();
        if (tid == 0) {
            float m = red[0];
            #pragma unroll
            for (int i = 1; i < 8; i++) m = fmaxf(m, red[i]);
            atomicMax(&g_absmax[which - 1], __float_as_uint(m));
        }
    }

    int rA = m0 + wr + gq;
    int col0 = h*64 + tg*2;
    if (which == 0) {
        __half* hA = g_qf + (size_t)rA * DIM + col0;
        __half* hB = hA + 8 * DIM;
        #pragma unroll
        for (int nb = 0; nb < 8; nb++) {
            *reinterpret_cast<uint32_t*>(hA + nb*8) = hpack(acc[nb*4+0]*QSCL, acc[nb*4+1]*QSCL);
            *reinterpret_cast<uint32_t*>(hB + nb*8) = hpack(acc[nb*4+2]*QSCL, acc[nb*4+3]*QSCL);
        }
    } else {
        float* fA = ((which == 1) ? g_kd : g_vd) + (size_t)rA * DIM + col0;
        float* fB = fA + 8 * DIM;
        #pragma unroll
        for (int nb = 0; nb < 8; nb++) {
            *reinterpret_cast<float2*>(fA + nb*8) = make_float2(acc[nb*4+0], acc[nb*4+1]);
            *reinterpret_cast<float2*>(fB + nb*8) = make_float2(acc[nb*4+2], acc[nb*4+3]);
        }
    }
}

// quant + dequant -> single fp16 (fused K/V via blockIdx.y)
__global__ void quant_kernel(const float* __restrict__ qjl)
{
    int which = blockIdx.y;
    const float* xdat = which ? g_vd : g_kd;
    __half* out = which ? g_vf : g_kf;
    float xmax = __uint_as_float(g_absmax[which]) + 1e-8f;
    float qsc  = qjl[0] * xmax;
    size_t i4 = (size_t)blockIdx.x * blockDim.x + threadIdx.x;
    float4 v = reinterpret_cast<const float4*>(xdat)[i4];
    float vv[4] = {v.x, v.y, v.z, v.w};
    #pragma unroll
    for (int t = 0; t < 4; t++) {
        float xs = vv[t] / xmax * 3.5f;
        float xq = rintf(xs * 4.0f) * 0.25f;
        xq = fminf(3.5f, fmaxf(-3.5f, xq));
        float r  = xs - xq;
        float sg = (r > 0.0f) ? 1.0f : ((r < 0.0f) ? -1.0f : 0.0f);
        vv[t] = (xq + sg * qsc) / 3.5f * xmax;
    }
    reinterpret_cast<uint2*>(out)[i4] = make_uint2(hpack(vv[0], vv[1]), hpack(vv[2], vv[3]));
}

// ===================== HMMA flash attention + fused inverse rotation =====================
// BM=64 (4 warps x 16 rows), BN=64 keys/tile, 32 tiles. 128 threads, 2 CTAs/SM.
// Q pre-scaled by QSCL -> softmax is bare ex2. Epilogue: O normalized -> fp16 A-frags
// -> inverse rotation GEMM (Ri hi/lo in reused stage smem) -> fp32 d_out.
#define STG   32768
#define SVH   16384
#define ATT_SMEM (3*STG)
__global__ void __launch_bounds__(128, 2) attn_kernel(
    const __half* __restrict__ qf_g, const __half* __restrict__ kf_g,
    const __half* __restrict__ vf_g, float* __restrict__ og)
{
    extern __shared__ char smc[];
    uint32_t smb = smem_u32(smc);

    int tid = threadIdx.x;
    int w = tid >> 5, lane = tid & 31;
    int l = lane & 7, g = lane >> 3;
    int ga = (g & 1) << 3;
    int gb = g >> 1;

    size_t base = (size_t)blockIdx.y * SEQ * DIM;
    int q0 = blockIdx.x * 64;

    // ---- load Q fragments via smem staging (stage-0 region) ----
    uint32_t qf[8][4];
    {
        for (int f = tid; f < 1024; f += 128) {
            int r = f >> 4, c = f & 15;
            *reinterpret_cast<uint4*>(smc + r*256 + ((c ^ (r & 7)) << 4)) =
                *reinterpret_cast<const uint4*>(qf_g + base + (size_t)(q0 + r)*DIM + c*8);
        }
        __syncthreads();
        int row = w*16 + ga + l;
        uint32_t rbase = smb + row*256;
        int rx = row & 7;
        #pragma unroll
        for (int k8 = 0; k8 < 8; k8++) {
            int ch = k8*2 + gb;
            ldm_x4(qf[k8], rbase + ((ch ^ rx) << 4));
        }
        __syncthreads();
    }

    // ---- prefetch tiles 0,1 into stages 0,1 ----
    #pragma unroll
    for (int pt = 0; pt < 2; pt++) {
        uint32_t sb = smb + pt * STG;
        int kt = pt * 64;
        #pragma unroll
        for (int it = 0; it < 8; it++) {
            int f = tid + it*128;
            int r = f >> 4, c = f & 15;
            size_t gi = base + (size_t)(kt + r)*DIM + c*8;
            uint32_t so = r*256 + ((c ^ (r & 7)) << 4);
            cpa16(sb + so,       kf_g + gi);
            cpa16(sb + SVH + so, vf_g + gi);
        }
        cpa_commit();
    }

    float o[64];
    #pragma unroll
    for (int i = 0; i < 64; i++) o[i] = 0.0f;
    float lsA = 0.0f, lsB = 0.0f;

    int cur = 0, nxt2 = 2;
    for (int t = 0; t < 32; t++) {
        if (t < 30) {
            uint32_t sb = smb + nxt2 * STG;
            int kt2 = (t + 2) * 64;
            #pragma unroll
            for (int it = 0; it < 8; it++) {
                int f = tid + it*128;
                int r = f >> 4, c = f & 15;
                size_t gi = base + (size_t)(kt2 + r)*DIM + c*8;
                uint32_t so = r*256 + ((c ^ (r & 7)) << 4);
                cpa16(sb + so,       kf_g + gi);
                cpa16(sb + SVH + so, vf_g + gi);
            }
            cpa_commit();
            cpa_wait<2>();
        } else if (t == 30) {
            cpa_wait<1>();
        } else {
            cpa_wait<0>();
        }
        __syncthreads();

        uint32_t kb = smb + cur * STG;

        // ---- S = Qf * Kf ----
        float s[32];
        #pragma unroll
        for (int i = 0; i < 32; i++) s[i] = 0.0f;
        #pragma unroll
        for (int k8 = 0; k8 < 8; k8++) {
            #pragma unroll
            for (int np = 0; np < 4; np++) {
                int row = np*16 + (gb << 3) + l;
                int ch = k8*2 + (g & 1);
                uint32_t b[4];
                ldm_x4(b, kb + row*256 + ((ch ^ (row & 7)) << 4));
                mma16816h(&s[np*8],     qf[k8], b);
                mma16816h(&s[np*8 + 4], qf[k8], b + 2);
            }
        }

        // ---- softmax: p = 2^s (Q pre-scaled) ----
        #pragma unroll
        for (int nb = 0; nb < 8; nb++) {
            float p0 = ex2(s[nb*4+0]), p1 = ex2(s[nb*4+1]);
            float p2 = ex2(s[nb*4+2]), p3 = ex2(s[nb*4+3]);
            s[nb*4+0] = p0; s[nb*4+1] = p1; s[nb*4+2] = p2; s[nb*4+3] = p3;
            lsA += p0 + p1;
            lsB += p2 + p3;
        }
        uint32_t pf[4][4];
        #pragma unroll
        for (int kk = 0; kk < 4; kk++) {
            pf[kk][0] = hpack(s[8*kk+0], s[8*kk+1]);
            pf[kk][1] = hpack(s[8*kk+2], s[8*kk+3]);
            pf[kk][2] = hpack(s[8*kk+4], s[8*kk+5]);
            pf[kk][3] = hpack(s[8*kk+6], s[8*kk+7]);
        }

        // ---- O += Pf * Vf ----
        {
            uint32_t vb = kb + SVH;
            #pragma unroll
            for (int kk = 0; kk < 4; kk++) {
                #pragma unroll
                for (int nd = 0; nd < 8; nd++) {
                    int row = kk*16 + ga + l;
                    int ch = nd*2 + gb;
                    uint32_t b[4];
                    ldm_x4t(b, vb + row*256 + ((ch ^ (row & 7)) << 4));
                    mma16816h(&o[nd*8],     pf[kk], b);
                    mma16816h(&o[nd*8 + 4], pf[kk], b + 2);
                }
            }
        }
        __syncthreads();

        if (++cur == 3) cur = 0;
        if (++nxt2 == 3) nxt2 = 0;
    }

    // ---- epilogue: normalize -> fp16 A-frags; load Ri; inverse GEMM; store fp32 ----
    lsA += __shfl_xor_sync(0xffffffffu, lsA, 1);
    lsA += __shfl_xor_sync(0xffffffffu, lsA, 2);
    lsB += __shfl_xor_sync(0xffffffffu, lsB, 1);
    lsB += __shfl_xor_sync(0xffffffffu, lsB, 2);
    float invA = 1.0f / lsA, invB = 1.0f / lsB;

    // Load Ri hi/lo into the (now free) stage-0/1 smem. The mainloop's final
    // __syncthreads guarantees all warps are done with the stage buffers.
    for (int f = tid; f < 2048; f += 128) {
        cpa16(smb + f*16,         reinterpret_cast<const char*>(g_Ri_hi) + f*16);
        cpa16(smb + 32768 + f*16, reinterpret_cast<const char*>(g_Ri_lo) + f*16);
    }
    cpa_commit();

    // O C-fragments -> A-fragments (values identical to the old fp16 g_of store).
    uint32_t af[8][4];
    #pragma unroll
    for (int kc = 0; kc < 8; kc++) {
        af[kc][0] = hpack(o[8*kc+0]*invA, o[8*kc+1]*invA);
        af[kc][1] = hpack(o[8*kc+2]*invB, o[8*kc+3]*invB);
        af[kc][2] = hpack(o[8*kc+4]*invA, o[8*kc+5]*invA);
        af[kc][3] = hpack(o[8*kc+6]*invB, o[8*kc+7]*invB);
    }

    cpa_wait<0>();
    __syncthreads();

    // Inverse rotation: each warp computes its 16 rows x 128 cols in two halves.
    #pragma unroll
    for (int h2 = 0; h2 < 2; h2++) {
        float a2[32];
        #pragma unroll
        for (int i = 0; i < 32; i++) a2[i] = 0.0f;

        #pragma unroll
        for (int k8 = 0; k8 < 8; k8++) {
            #pragma unroll
            for (int np = 0; np < 4; np++) {
                int brow = h2*64 + np*16 + (gb << 3) + l;
                int ch = k8*2 + (g & 1);
                uint32_t off = brow*256 + ((ch ^ (brow & 7)) << 4);
                uint32_t bh[4], bl[4];
                ldm_x4(bh, smb + off);
                ldm_x4(bl, smb + 32768 + off);
                mma16816h(&a2[np*8],     af[k8], bh);
                mma16816h(&a2[np*8 + 4], af[k8], bh + 2);
                mma16816h(&a2[np*8],     af[k8], bl);
                mma16816h(&a2[np*8 + 4], af[k8], bl + 2);
            }
        }

        int rA = q0 + w*16 + (lane >> 2);
        int col0 = h2*64 + (lane & 3)*2;
        float* fA = og + base + (size_t)rA * DIM + col0;
        float* fB = fA + 8 * DIM;
        #pragma unroll
        for (int nb = 0; nb < 8; nb++) {
            *reinterpret_cast<float2*>(fA + nb*8) = make_float2(a2[nb*4+0], a2[nb*4+1]);
            *reinterpret_cast<float2*>(fB + nb*8) = make_float2(a2[nb*4+2], a2[nb*4+3]);
        }
    }
}

// ------------------------------------------------------------------
extern "C" void kernel_launch(void* const* d_in, const int* in_sizes, int n_in,
                              void* d_out, int out_size)
{
    const float* q   = (const float*)d_in[0];
    const float* k   = (const float*)d_in[1];
    const float* v   = (const float*)d_in[2];
    const float* R   = (const float*)d_in[3];
    const float* qjl = (const float*)d_in[4];

    __half *qf, *kf, *vf;
    cudaGetSymbolAddress((void**)&qf, g_qf);
    cudaGetSymbolAddress((void**)&kf, g_kf);
    cudaGetSymbolAddress((void**)&vf, g_vf);

    cudaFuncSetAttribute(rotfwd_kernel, cudaFuncAttributeMaxDynamicSharedMemorySize, ROT_SMEM);
    cudaFuncSetAttribute(attn_kernel,   cudaFuncAttributeMaxDynamicSharedMemorySize, ATT_SMEM);

    prepR_kernel<<<128, 128>>>(R);

    rotfwd_kernel<<<dim3(NTOK/64, 3), 256, ROT_SMEM>>>(q, k, v);

    quant_kernel<<<dim3(NELEM/4/256, 2), 256>>>(qjl);

    attn_kernel<<<dim3(SEQ/64, BHN), 128, ATT_SMEM>>>(qf, kf, vf, (float*)d_out);
}

// round 15
// speedup vs baseline: 1.1400x; 1.0521x over previous
#include <cuda_runtime.h>
#include <cuda_bf16.h>
#include <cuda_fp16.h>
#include <cstdint>

#define BHN 32
#define SEQ 2048
#define DIM 128
#define NTOK (BHN*SEQ)          // 65536
#define NELEM (NTOK*DIM)        // 8388608

// ---- scratch (static device globals; no runtime allocation) ----
__device__ float g_kd[NELEM];
__device__ float g_vd[NELEM];
__device__ unsigned int g_absmax[2];
__device__ __align__(16) __half g_qf[NELEM];
__device__ __align__(16) __half g_kf[NELEM];
__device__ __align__(16) __half g_vf[NELEM];
// pre-swizzled fp16 hi/lo rotation operands (B layout [n][k], 256B pitch)
__device__ __align__(16) __half g_Rf_hi[DIM*DIM];
__device__ __align__(16) __half g_Rf_lo[DIM*DIM];
__device__ __align__(16) __half g_Ri_hi[DIM*DIM];
__device__ __align__(16) __half g_Ri_lo[DIM*DIM];

// 1/sqrt(128) * log2(e): fold into Q so softmax is a bare ex2
#define QSCL 0.12751744750522672f

// ================= helpers =================
__device__ __forceinline__ uint32_t smem_u32(const void* p) {
    uint32_t a;
    asm("{ .reg .u64 t; cvta.to.shared.u64 t, %1; cvt.u32.u64 %0, t; }" : "=r"(a) : "l"(p));
    return a;
}
__device__ __forceinline__ void ldm_x4(uint32_t* r, uint32_t addr) {
    asm volatile("ldmatrix.sync.aligned.m8n8.x4.shared.b16 {%0,%1,%2,%3}, [%4];"
        : "=r"(r[0]), "=r"(r[1]), "=r"(r[2]), "=r"(r[3]) : "r"(addr));
}
__device__ __forceinline__ void ldm_x4t(uint32_t* r, uint32_t addr) {
    asm volatile("ldmatrix.sync.aligned.m8n8.x4.trans.shared.b16 {%0,%1,%2,%3}, [%4];"
        : "=r"(r[0]), "=r"(r[1]), "=r"(r[2]), "=r"(r[3]) : "r"(addr));
}
__device__ __forceinline__ void mma16816h(float* c, const uint32_t* a, const uint32_t* b) {
    asm volatile("mma.sync.aligned.m16n8k16.row.col.f32.f16.f16.f32 "
        "{%0,%1,%2,%3}, {%4,%5,%6,%7}, {%8,%9}, {%0,%1,%2,%3};"
        : "+f"(c[0]), "+f"(c[1]), "+f"(c[2]), "+f"(c[3])
        : "r"(a[0]), "r"(a[1]), "r"(a[2]), "r"(a[3]), "r"(b[0]), "r"(b[1]));
}
__device__ __forceinline__ float ex2(float x) {
    float y;
    asm("ex2.approx.f32 %0, %1;" : "=f"(y) : "f"(x));
    return y;
}
__device__ __forceinline__ uint32_t hpack(float a, float b) {
    __half2 h = __floats2half2_rn(a, b);
    return *reinterpret_cast<uint32_t*>(&h);
}
__device__ __forceinline__ void split2(float2 p, uint32_t& hi, uint32_t& lo) {
    __half2 h = __floats2half2_rn(p.x, p.y);
    hi = *reinterpret_cast<uint32_t*>(&h);
    lo = hpack(p.x - __half2float(h.x), p.y - __half2float(h.y));
}
__device__ __forceinline__ void cpa16(uint32_t d, const void* s) {
    asm volatile("cp.async.cg.shared.global [%0], [%1], 16;" :: "r"(d), "l"(s));
}
__device__ __forceinline__ void cpa_commit() {
    asm volatile("cp.async.commit_group;" ::: "memory");
}
template<int N> __device__ __forceinline__ void cpa_wait() {
    asm volatile("cp.async.wait_group %0;" :: "n"(N) : "memory");
}

// ------------------------------------------------------------------
// Build pre-swizzled fp16 hi/lo B operands; also reset absmax.
__global__ void prepR_kernel(const float* __restrict__ R) {
    int idx = blockIdx.x * 128 + threadIdx.x;   // 16384
    if (idx < 2) g_absmax[idx] = 0u;
    int n = idx >> 7, k = idx & 127;
    float fv = R[k*DIM + n];   // Bfwd[n][k] = R[k][n]
    float iv = R[n*DIM + k];   // Binv[n][k] = R[n][k]
    int c = k >> 3;
    uint32_t off = (uint32_t)(n*256 + ((c ^ (n & 7)) << 4) + (k & 7)*2);
    __half fh = __float2half_rn(fv);
    __half ih = __float2half_rn(iv);
    *reinterpret_cast<__half*>(reinterpret_cast<char*>(g_Rf_hi) + off) = fh;
    *reinterpret_cast<__half*>(reinterpret_cast<char*>(g_Rf_lo) + off) = __float2half_rn(fv - __half2float(fh));
    *reinterpret_cast<__half*>(reinterpret_cast<char*>(g_Ri_hi) + off) = ih;
    *reinterpret_cast<__half*>(reinterpret_cast<char*>(g_Ri_lo) + off) = __float2half_rn(iv - __half2float(ih));
}

// ===================== HMMA forward rotation (fused q/k/v) =====================
// 64 rows/CTA, 256 threads (8 warps). warp w: rows (w&3)*16, n-half (w>>2)*64.
// X staged through smem via coalesced cp.async (overlapped with R copy);
// A-fragments built per-k8 from smem (same values/order as before -> bit-identical).
// blockIdx.y: 0=q (fp16 out, pre-scaled by QSCL), 1=k, 2=v (fp32 out + absmax).
#define RXOFF 65536                 // X staging offset
#define XPITCH 528                  // 132 floats per row (pad vs 128 to stagger banks)
#define ROT_SMEM (RXOFF + 64*XPITCH)  // 99328
__global__ void __launch_bounds__(256, 2) rotfwd_kernel(
    const float* __restrict__ xq, const float* __restrict__ xk, const float* __restrict__ xv)
{
    extern __shared__ char smc[];
    uint32_t smb = smem_u32(smc);
    int which = blockIdx.y;
    const float* x = (which == 0) ? xq : (which == 1) ? xk : xv;
    int tid = threadIdx.x;
    int w = tid >> 5, lane = tid & 31;
    int gq = lane >> 2, tg = lane & 3;
    int l8 = lane & 7, g8 = lane >> 3;
    int gb = g8 >> 1, gA = g8 & 1;
    int h  = w >> 2;
    int wr = (w & 3) * 16;
    int m0 = blockIdx.x * 64;

    // R hi/lo copy + coalesced X copy, one commit group
    for (int f = tid; f < 2048; f += 256) {
        cpa16(smb + f*16,         reinterpret_cast<const char*>(g_Rf_hi) + f*16);
        cpa16(smb + 32768 + f*16, reinterpret_cast<const char*>(g_Rf_lo) + f*16);
    }
    for (int f = tid; f < 2048; f += 256) {
        int r = f >> 5, c4 = f & 31;
        cpa16(smb + RXOFF + r*XPITCH + c4*16, x + (size_t)(m0 + r)*DIM + c4*4);
    }
    cpa_commit();
    cpa_wait<0>();
    __syncthreads();

    const float* xr0 = reinterpret_cast<const float*>(smc + RXOFF + (wr + gq) * XPITCH);
    const float* xr8 = reinterpret_cast<const float*>(smc + RXOFF + (wr + gq + 8) * XPITCH);

    float acc[32];
    #pragma unroll
    for (int i = 0; i < 32; i++) acc[i] = 0.0f;

    #pragma unroll
    for (int k8 = 0; k8 < 8; k8++) {
        // Build this k8's A fragments from staged X (bit-identical split)
        uint32_t ah[4], al[4];
        {
            int c0 = k8*16 + tg*2;
            float2 p00 = *reinterpret_cast<const float2*>(xr0 + c0);
            float2 p10 = *reinterpret_cast<const float2*>(xr8 + c0);
            float2 p01 = *reinterpret_cast<const float2*>(xr0 + c0 + 8);
            float2 p11 = *reinterpret_cast<const float2*>(xr8 + c0 + 8);
            split2(p00, ah[0], al[0]);
            split2(p10, ah[1], al[1]);
            split2(p01, ah[2], al[2]);
            split2(p11, ah[3], al[3]);
        }
        #pragma unroll
        for (int np = 0; np < 4; np++) {
            int brow = h*64 + np*16 + (gb << 3) + l8;
            int ch = k8*2 + gA;
            uint32_t off = brow*256 + ((ch ^ (brow & 7)) << 4);
            uint32_t bh[4], bl[4];
            ldm_x4(bh, smb + off);
            ldm_x4(bl, smb + 32768 + off);
            mma16816h(&acc[np*8],     ah, bh);
            mma16816h(&acc[np*8 + 4], ah, bh + 2);
            mma16816h(&acc[np*8],     ah, bl);
            mma16816h(&acc[np*8 + 4], ah, bl + 2);
            mma16816h(&acc[np*8],     al, bh);
            mma16816h(&acc[np*8 + 4], al, bh + 2);
        }
    }

    if (which > 0) {
        float mx = 0.0f;
        #pragma unroll
        for (int i = 0; i < 32; i++) mx = fmaxf(mx, fabsf(acc[i]));
        #pragma unroll
        for (int o = 16; o; o >>= 1) mx = fmaxf(mx, __shfl_xor_sync(0xffffffffu, mx, o));
        __shared__ float red[8];
        if (lane == 0) red[w] = mx;
        __syncthreads();
        if (tid == 0) {
            float m = red[0];
            #pragma unroll
            for (int i = 1; i < 8; i++) m = fmaxf(m, red[i]);
            atomicMax(&g_absmax[which - 1], __float_as_uint(m));
        }
    }

    int rA = m0 + wr + gq;
    int col0 = h*64 + tg*2;
    if (which == 0) {
        __half* hA = g_qf + (size_t)rA * DIM + col0;
        __half* hB = hA + 8 * DIM;
        #pragma unroll
        for (int nb = 0; nb < 8; nb++) {
            *reinterpret_cast<uint32_t*>(hA + nb*8) = hpack(acc[nb*4+0]*QSCL, acc[nb*4+1]*QSCL);
            *reinterpret_cast<uint32_t*>(hB + nb*8) = hpack(acc[nb*4+2]*QSCL, acc[nb*4+3]*QSCL);
        }
    } else {
        float* fA = ((which == 1) ? g_kd : g_vd) + (size_t)rA * DIM + col0;
        float* fB = fA + 8 * DIM;
        #pragma unroll
        for (int nb = 0; nb < 8; nb++) {
            *reinterpret_cast<float2*>(fA + nb*8) = make_float2(acc[nb*4+0], acc[nb*4+1]);
            *reinterpret_cast<float2*>(fB + nb*8) = make_float2(acc[nb*4+2], acc[nb*4+3]);
        }
    }
}

// quant + dequant -> single fp16 (fused K/V via blockIdx.y)
__global__ void quant_kernel(const float* __restrict__ qjl)
{
    int which = blockIdx.y;
    const float* xdat = which ? g_vd : g_kd;
    __half* out = which ? g_vf : g_kf;
    float xmax = __uint_as_float(g_absmax[which]) + 1e-8f;
    float qsc  = qjl[0] * xmax;
    size_t i4 = (size_t)blockIdx.x * blockDim.x + threadIdx.x;
    float4 v = reinterpret_cast<const float4*>(xdat)[i4];
    float vv[4] = {v.x, v.y, v.z, v.w};
    #pragma unroll
    for (int t = 0; t < 4; t++) {
        float xs = vv[t] / xmax * 3.5f;
        float xq = rintf(xs * 4.0f) * 0.25f;
        xq = fminf(3.5f, fmaxf(-3.5f, xq));
        float r  = xs - xq;
        float sg = (r > 0.0f) ? 1.0f : ((r < 0.0f) ? -1.0f : 0.0f);
        vv[t] = (xq + sg * qsc) / 3.5f * xmax;
    }
    reinterpret_cast<uint2*>(out)[i4] = make_uint2(hpack(vv[0], vv[1]), hpack(vv[2], vv[3]));
}

// ===================== HMMA flash attention + fused inverse rotation =====================
// BM=64 (4 warps x 16 rows), BN=64 keys/tile, 32 tiles. 128 threads, 2 CTAs/SM.
// Q pre-scaled by QSCL -> softmax is bare ex2. Epilogue: O normalized -> fp16 A-frags
// -> inverse rotation GEMM (Ri hi/lo in reused stage smem) -> fp32 d_out.
#define STG   32768
#define SVH   16384
#define ATT_SMEM (3*STG)
__global__ void __launch_bounds__(128, 2) attn_kernel(
    const __half* __restrict__ qf_g, const __half* __restrict__ kf_g,
    const __half* __restrict__ vf_g, float* __restrict__ og)
{
    extern __shared__ char smc[];
    uint32_t smb = smem_u32(smc);

    int tid = threadIdx.x;
    int w = tid >> 5, lane = tid & 31;
    int l = lane & 7, g = lane >> 3;
    int ga = (g & 1) << 3;
    int gb = g >> 1;

    size_t base = (size_t)blockIdx.y * SEQ * DIM;
    int q0 = blockIdx.x * 64;

    // ---- load Q fragments via smem staging (stage-0 region) ----
    uint32_t qf[8][4];
    {
        for (int f = tid; f < 1024; f += 128) {
            int r = f >> 4, c = f & 15;
            *reinterpret_cast<uint4*>(smc + r*256 + ((c ^ (r & 7)) << 4)) =
                *reinterpret_cast<const uint4*>(qf_g + base + (size_t)(q0 + r)*DIM + c*8);
        }
        __syncthreads();
        int row = w*16 + ga + l;
        uint32_t rbase = smb + row*256;
        int rx = row & 7;
        #pragma unroll
        for (int k8 = 0; k8 < 8; k8++) {
            int ch = k8*2 + gb;
            ldm_x4(qf[k8], rbase + ((ch ^ rx) << 4));
        }
        __syncthreads();
    }

    // ---- prefetch tiles 0,1 into stages 0,1 ----
    #pragma unroll
    for (int pt = 0; pt < 2; pt++) {
        uint32_t sb = smb + pt * STG;
        int kt = pt * 64;
        #pragma unroll
        for (int it = 0; it < 8; it++) {
            int f = tid + it*128;
            int r = f >> 4, c = f & 15;
            size_t gi = base + (size_t)(kt + r)*DIM + c*8;
            uint32_t so = r*256 + ((c ^ (r & 7)) << 4);
            cpa16(sb + so,       kf_g + gi);
            cpa16(sb + SVH + so, vf_g + gi);
        }
        cpa_commit();
    }

    float o[64];
    #pragma unroll
    for (int i = 0; i < 64; i++) o[i] = 0.0f;
    float lsA = 0.0f, lsB = 0.0f;

    int cur = 0, nxt2 = 2;
    for (int t = 0; t < 32; t++) {
        if (t < 30) {
            uint32_t sb = smb + nxt2 * STG;
            int kt2 = (t + 2) * 64;
            #pragma unroll
            for (int it = 0; it < 8; it++) {
                int f = tid + it*128;
                int r = f >> 4, c = f & 15;
                size_t gi = base + (size_t)(kt2 + r)*DIM + c*8;
                uint32_t so = r*256 + ((c ^ (r & 7)) << 4);
                cpa16(sb + so,       kf_g + gi);
                cpa16(sb + SVH + so, vf_g + gi);
            }
            cpa_commit();
            cpa_wait<2>();
        } else if (t == 30) {
            cpa_wait<1>();
        } else {
            cpa_wait<0>();
        }
        __syncthreads();

        uint32_t kb = smb + cur * STG;

        // ---- S = Qf * Kf ----
        float s[32];
        #pragma unroll
        for (int i = 0; i < 32; i++) s[i] = 0.0f;
        #pragma unroll
        for (int k8 = 0; k8 < 8; k8++) {
            #pragma unroll
            for (int np = 0; np < 4; np++) {
                int row = np*16 + (gb << 3) + l;
                int ch = k8*2 + (g & 1);
                uint32_t b[4];
                ldm_x4(b, kb + row*256 + ((ch ^ (row & 7)) << 4));
                mma16816h(&s[np*8],     qf[k8], b);
                mma16816h(&s[np*8 + 4], qf[k8], b + 2);
            }
        }

        // ---- softmax: p = 2^s (Q pre-scaled) ----
        #pragma unroll
        for (int nb = 0; nb < 8; nb++) {
            float p0 = ex2(s[nb*4+0]), p1 = ex2(s[nb*4+1]);
            float p2 = ex2(s[nb*4+2]), p3 = ex2(s[nb*4+3]);
            s[nb*4+0] = p0; s[nb*4+1] = p1; s[nb*4+2] = p2; s[nb*4+3] = p3;
            lsA += p0 + p1;
            lsB += p2 + p3;
        }
        uint32_t pf[4][4];
        #pragma unroll
        for (int kk = 0; kk < 4; kk++) {
            pf[kk][0] = hpack(s[8*kk+0], s[8*kk+1]);
            pf[kk][1] = hpack(s[8*kk+2], s[8*kk+3]);
            pf[kk][2] = hpack(s[8*kk+4], s[8*kk+5]);
            pf[kk][3] = hpack(s[8*kk+6], s[8*kk+7]);
        }

        // ---- O += Pf * Vf ----
        {
            uint32_t vb = kb + SVH;
            #pragma unroll
            for (int kk = 0; kk < 4; kk++) {
                #pragma unroll
                for (int nd = 0; nd < 8; nd++) {
                    int row = kk*16 + ga + l;
                    int ch = nd*2 + gb;
                    uint32_t b[4];
                    ldm_x4t(b, vb + row*256 + ((ch ^ (row & 7)) << 4));
                    mma16816h(&o[nd*8],     pf[kk], b);
                    mma16816h(&o[nd*8 + 4], pf[kk], b + 2);
                }
            }
        }
        __syncthreads();

        if (++cur == 3) cur = 0;
        if (++nxt2 == 3) nxt2 = 0;
    }

    // ---- epilogue: normalize -> fp16 A-frags; load Ri; inverse GEMM; store fp32 ----
    lsA += __shfl_xor_sync(0xffffffffu, lsA, 1);
    lsA += __shfl_xor_sync(0xffffffffu, lsA, 2);
    lsB += __shfl_xor_sync(0xffffffffu, lsB, 1);
    lsB += __shfl_xor_sync(0xffffffffu, lsB, 2);
    float invA = 1.0f / lsA, invB = 1.0f / lsB;

    // Load Ri hi/lo into the (now free) stage-0/1 smem. The mainloop's final
    // __syncthreads guarantees all warps are done with the stage buffers.
    for (int f = tid; f < 2048; f += 128) {
        cpa16(smb + f*16,         reinterpret_cast<const char*>(g_Ri_hi) + f*16);
        cpa16(smb + 32768 + f*16, reinterpret_cast<const char*>(g_Ri_lo) + f*16);
    }
    cpa_commit();

    // O C-fragments -> A-fragments (values identical to the old fp16 g_of store).
    uint32_t af[8][4];
    #pragma unroll
    for (int kc = 0; kc < 8; kc++) {
        af[kc][0] = hpack(o[8*kc+0]*invA, o[8*kc+1]*invA);
        af[kc][1] = hpack(o[8*kc+2]*invB, o[8*kc+3]*invB);
        af[kc][2] = hpack(o[8*kc+4]*invA, o[8*kc+5]*invA);
        af[kc][3] = hpack(o[8*kc+6]*invB, o[8*kc+7]*invB);
    }

    cpa_wait<0>();
    __syncthreads();

    // Inverse rotation: each warp computes its 16 rows x 128 cols in two halves.
    #pragma unroll
    for (int h2 = 0; h2 < 2; h2++) {
        float a2[32];
        #pragma unroll
        for (int i = 0; i < 32; i++) a2[i] = 0.0f;

        #pragma unroll
        for (int k8 = 0; k8 < 8; k8++) {
            #pragma unroll
            for (int np = 0; np < 4; np++) {
                int brow = h2*64 + np*16 + (gb << 3) + l;
                int ch = k8*2 + (g & 1);
                uint32_t off = brow*256 + ((ch ^ (brow & 7)) << 4);
                uint32_t bh[4], bl[4];
                ldm_x4(bh, smb + off);
                ldm_x4(bl, smb + 32768 + off);
                mma16816h(&a2[np*8],     af[k8], bh);
                mma16816h(&a2[np*8 + 4], af[k8], bh + 2);
                mma16816h(&a2[np*8],     af[k8], bl);
                mma16816h(&a2[np*8 + 4], af[k8], bl + 2);
            }
        }

        int rA = q0 + w*16 + (lane >> 2);
        int col0 = h2*64 + (lane & 3)*2;
        float* fA = og + base + (size_t)rA * DIM + col0;
        float* fB = fA + 8 * DIM;
        #pragma unroll
        for (int nb = 0; nb < 8; nb++) {
            *reinterpret_cast<float2*>(fA + nb*8) = make_float2(a2[nb*4+0], a2[nb*4+1]);
            *reinterpret_cast<float2*>(fB + nb*8) = make_float2(a2[nb*4+2], a2[nb*4+3]);
        }
    }
}

// ------------------------------------------------------------------
extern "C" void kernel_launch(void* const* d_in, const int* in_sizes, int n_in,
                              void* d_out, int out_size)
{
    const float* q   = (const float*)d_in[0];
    const float* k   = (const float*)d_in[1];
    const float* v   = (const float*)d_in[2];
    const float* R   = (const float*)d_in[3];
    const float* qjl = (const float*)d_in[4];

    __half *qf, *kf, *vf;
    cudaGetSymbolAddress((void**)&qf, g_qf);
    cudaGetSymbolAddress((void**)&kf, g_kf);
    cudaGetSymbolAddress((void**)&vf, g_vf);

    cudaFuncSetAttribute(rotfwd_kernel, cudaFuncAttributeMaxDynamicSharedMemorySize, ROT_SMEM);
    cudaFuncSetAttribute(attn_kernel,   cudaFuncAttributeMaxDynamicSharedMemorySize, ATT_SMEM);

    prepR_kernel<<<128, 128>>>(R);

    rotfwd_kernel<<<dim3(NTOK/64, 3), 256, ROT_SMEM>>>(q, k, v);

    quant_kernel<<<dim3(NELEM/4/256, 2), 256>>>(qjl);

    attn_kernel<<<dim3(SEQ/64, BHN), 128, ATT_SMEM>>>(qf, kf, vf, (float*)d_out);
}